// round 4
// baseline (speedup 1.0000x reference)
#include <cuda_runtime.h>
#include <math.h>

typedef unsigned long long ull;

// Problem constants
#define BMT 32      // B*M
#define NN 1024     // nodes
#define DD 128      // input dim
#define PP 64       // projection dim
#define NC 10       // clusters
#define FF 128      // output features
#define KK 10       // k neighbors
#define NSPLIT 4    // kNN candidate-dimension splits
#define JCHUNK (NN / NSPLIT)
#define INV_SQRT11 0.30151134457776363f

// ---------------- scratch (device globals: allocation-free) ----------------
__device__ float g_Z[BMT * NN * PP];        // projected points
__device__ float g_sq[BMT * NN];            // squared norms
__device__ int   g_idx[BMT * NN * KK];      // knn indices
__device__ float g_Hc[BMT * NN * NC];       // cluster softmax probs
__device__ float g_Xs[BMT * NN * FF];       // X_trans * 1/sqrt(11)
__device__ int   g_cnt[BMT * NN];           // per-edge (column) degree of H_knn
__device__ int   g_start[BMT * NN];         // CSR starts
__device__ int   g_fill[BMT * NN];          // CSR fill cursors
__device__ int   g_list[BMT * NN * KK];     // CSR column lists (rows per edge)
__device__ float g_tmpE[BMT * NN * FF];     // De_inv * (H_knn^T @ Xs)
__device__ float g_tmpC[BMT * NC * FF];     // H_cluster^T @ Xs (unscaled)
__device__ float g_DeC[BMT * NC];           // cluster edge degrees
__device__ float g_pval[BMT * NN * NSPLIT * KK];  // partial top-10 scores
__device__ int   g_pidx[BMT * NN * NSPLIT * KK];  // partial top-10 indices

// ---------------- f32x2 helpers ----------------
__device__ __forceinline__ void fma2(ull& d, ull a, ull b) {
    asm("fma.rn.f32x2 %0, %1, %2, %3;" : "=l"(d) : "l"(a), "l"(b), "l"(d));
}
__device__ __forceinline__ ull dup2(float a) {
    ull d;
    unsigned r = __float_as_uint(a);
    asm("mov.b64 %0, {%1, %1};" : "=l"(d) : "r"(r));
    return d;
}
__device__ __forceinline__ void unpack2(ull v, float& lo, float& hi) {
    unsigned a, b;
    asm("mov.b64 {%0, %1}, %2;" : "=r"(a), "=r"(b) : "l"(v));
    lo = __uint_as_float(a);
    hi = __uint_as_float(b);
}

// ---------------- GEMM (f32x2 packed): out[bm,n,c] = (sum_d x*W + b) * scale
template <int MODE>
__global__ void __launch_bounds__(128) k_gemm(const float* __restrict__ X,
                                              const float* __restrict__ W,
                                              const float* __restrict__ bias,
                                              float scale) {
    constexpr int NCOLS = (MODE == 0) ? PP : FF;
    float* outp = (MODE == 0) ? g_Z : g_Xs;
    __shared__ __align__(16) float sAT[32][72];  // [k][row]
    __shared__ __align__(16) float sWT[32][72];  // [k][col]
    int bm = blockIdx.x;
    int row0 = blockIdx.y * 64;
    int col0 = blockIdx.z * 64;
    int b = bm >> 3, m = bm & 7;
    int tid = threadIdx.x;
    // fold in g_DeC zeroing (must precede k_cluster_sq's atomics; MODE 0 runs first)
    if (MODE == 0 && blockIdx.x == 0 && blockIdx.y == 0 && blockIdx.z == 0) {
        for (int i = tid; i < BMT * NC; i += 128) g_DeC[i] = 0.f;
    }
    int tr = tid >> 3;  // 0..15 -> 4 rows each
    int tc = tid & 7;   // 0..7  -> 8 cols each
    ull acc2[4][4] = {};
    const float* xbase = X + ((size_t)(b * NN) * 8 + m) * DD;
    for (int k0 = 0; k0 < DD; k0 += 32) {
        for (int t = tid; t < 64 * 32; t += 128) {
            int r = t >> 5, k = t & 31;
            sAT[k][r] = xbase[(size_t)(row0 + r) * 1024 + k0 + k];
            sWT[k][r] = W[(col0 + r) * DD + k0 + k];
        }
        __syncthreads();
#pragma unroll
        for (int k = 0; k < 32; k++) {
            float4 a4 = *(const float4*)&sAT[k][tr * 4];
            ulonglong2 wA = *(const ulonglong2*)&sWT[k][tc * 8];
            ulonglong2 wB = *(const ulonglong2*)&sWT[k][tc * 8 + 4];
            ull a0 = dup2(a4.x), a1 = dup2(a4.y), a2 = dup2(a4.z), a3 = dup2(a4.w);
            fma2(acc2[0][0], a0, wA.x); fma2(acc2[0][1], a0, wA.y);
            fma2(acc2[0][2], a0, wB.x); fma2(acc2[0][3], a0, wB.y);
            fma2(acc2[1][0], a1, wA.x); fma2(acc2[1][1], a1, wA.y);
            fma2(acc2[1][2], a1, wB.x); fma2(acc2[1][3], a1, wB.y);
            fma2(acc2[2][0], a2, wA.x); fma2(acc2[2][1], a2, wA.y);
            fma2(acc2[2][2], a2, wB.x); fma2(acc2[2][3], a2, wB.y);
            fma2(acc2[3][0], a3, wA.x); fma2(acc2[3][1], a3, wA.y);
            fma2(acc2[3][2], a3, wB.x); fma2(acc2[3][3], a3, wB.y);
        }
        __syncthreads();
    }
    float bv[8];
#pragma unroll
    for (int j = 0; j < 8; j++) bv[j] = bias[col0 + tc * 8 + j];
#pragma unroll
    for (int i = 0; i < 4; i++) {
        int n = row0 + tr * 4 + i;
        float f[8];
#pragma unroll
        for (int j2 = 0; j2 < 4; j2++) unpack2(acc2[i][j2], f[2 * j2], f[2 * j2 + 1]);
        float4 o0, o1;
        o0.x = (f[0] + bv[0]) * scale; o0.y = (f[1] + bv[1]) * scale;
        o0.z = (f[2] + bv[2]) * scale; o0.w = (f[3] + bv[3]) * scale;
        o1.x = (f[4] + bv[4]) * scale; o1.y = (f[5] + bv[5]) * scale;
        o1.z = (f[6] + bv[6]) * scale; o1.w = (f[7] + bv[7]) * scale;
        float* op = outp + ((size_t)bm * NN + n) * NCOLS + col0 + tc * 8;
        *(float4*)op = o0;
        *(float4*)(op + 4) = o1;
    }
}

// ---------------- K_cluster_sq: softmax + DeC + sq norm + zero cnt/tmpC ----
__global__ void __launch_bounds__(256) k_cluster_sq(const float* __restrict__ C) {
    __shared__ float sC[NC * PP];
    __shared__ float sDeC[NC];
    int tid = threadIdx.x;
    for (int t = tid; t < NC * PP; t += 256) sC[t] = C[t];
    if (tid < NC) sDeC[tid] = 0.f;
    __syncthreads();
    int row = blockIdx.x * 256 + tid;
    int bm = row >> 10;
    // zero accumulators used later
    g_cnt[row] = 0;
    for (int i = row; i < BMT * NC * FF; i += BMT * NN) g_tmpC[i] = 0.f;
    const float4* z4 = (const float4*)(g_Z + (size_t)row * PP);
    float acc[NC] = {};
    float sq = 0.f;
#pragma unroll
    for (int i = 0; i < 16; i++) {
        float4 v = z4[i];
        sq = fmaf(v.x, v.x, fmaf(v.y, v.y, fmaf(v.z, v.z, fmaf(v.w, v.w, sq))));
#pragma unroll
        for (int c = 0; c < NC; c++) {
            const float* cp = &sC[c * PP + i * 4];
            acc[c] = fmaf(v.x, cp[0], acc[c]);
            acc[c] = fmaf(v.y, cp[1], acc[c]);
            acc[c] = fmaf(v.z, cp[2], acc[c]);
            acc[c] = fmaf(v.w, cp[3], acc[c]);
        }
    }
    g_sq[row] = sq;
    float mx = acc[0];
#pragma unroll
    for (int c = 1; c < NC; c++) mx = fmaxf(mx, acc[c]);
    float p[NC], sum = 0.f;
#pragma unroll
    for (int c = 0; c < NC; c++) {
        p[c] = expf(acc[c] - mx);
        sum += p[c];
    }
    float inv = 1.f / sum;
#pragma unroll
    for (int c = 0; c < NC; c++) {
        p[c] *= inv;
        g_Hc[(size_t)row * NC + c] = p[c];
    }
#pragma unroll
    for (int c = 0; c < NC; c++)
#pragma unroll
        for (int o = 16; o; o >>= 1) p[c] += __shfl_xor_sync(0xffffffffu, p[c], o);
    if ((tid & 31) == 0) {
#pragma unroll
        for (int c = 0; c < NC; c++) atomicAdd(&sDeC[c], p[c]);
    }
    __syncthreads();
    if (tid < NC) atomicAdd(&g_DeC[bm * NC + tid], sDeC[tid]);
}

// ---------------- K2: Gram-GEMM tiles + streaming top-10 ----------------
// Block: 128 threads, 64 query rows, candidate chunk JCHUNK in tiles of 32.
// Score = sq[j] - 2*dot (sq[i] dropped: constant per row, ordering-invariant).
__global__ void __launch_bounds__(128) k_knn() {
    int bm = blockIdx.y >> 2;
    int split = blockIdx.y & 3;
    int row0 = blockIdx.x * 64;
    const ull* Zu = (const ull*)g_Z + (size_t)bm * NN * 32;

    __shared__ ull sQ[64][33];
    __shared__ ull sK[32][33];
    __shared__ float sD[64][33];
    __shared__ float ssq[32];

    int tid = threadIdx.x;
    // load query tile once (64 rows x 32 kpairs)
    for (int e = tid; e < 64 * 32; e += 128) {
        int r = e >> 5, kp = e & 31;
        sQ[r][kp] = Zu[(size_t)(row0 + r) * 32 + kp];
    }

    int tr = tid >> 3;   // 0..15: rows tr*4..tr*4+3
    int tc = tid & 7;    // 0..7:  cols tc*4..tc*4+3
    int myrow = tid & 63;
    int half = tid >> 6;

    float vals[KK];
    int idxs[KK];
#pragma unroll
    for (int k = 0; k < KK; k++) {
        vals[k] = __int_as_float(0x7f800000);
        idxs[k] = 0x7fffffff;
    }

    int jbeg = split * JCHUNK;
    for (int t0 = 0; t0 < JCHUNK; t0 += 32) {
        int j0g = jbeg + t0;
        __syncthreads();
        for (int e = tid; e < 32 * 32; e += 128) {
            int j = e >> 5, kp = e & 31;
            sK[j][kp] = Zu[(size_t)(j0g + j) * 32 + kp];
        }
        if (tid < 32) ssq[tid] = g_sq[bm * NN + j0g + tid];
        __syncthreads();

        ull acc[4][4] = {};
#pragma unroll
        for (int kp = 0; kp < 32; kp++) {
            ull q0 = sQ[tr * 4 + 0][kp];
            ull q1 = sQ[tr * 4 + 1][kp];
            ull q2 = sQ[tr * 4 + 2][kp];
            ull q3 = sQ[tr * 4 + 3][kp];
            ull c0 = sK[tc * 4 + 0][kp];
            ull c1 = sK[tc * 4 + 1][kp];
            ull c2 = sK[tc * 4 + 2][kp];
            ull c3 = sK[tc * 4 + 3][kp];
            fma2(acc[0][0], q0, c0); fma2(acc[0][1], q0, c1);
            fma2(acc[0][2], q0, c2); fma2(acc[0][3], q0, c3);
            fma2(acc[1][0], q1, c0); fma2(acc[1][1], q1, c1);
            fma2(acc[1][2], q1, c2); fma2(acc[1][3], q1, c3);
            fma2(acc[2][0], q2, c0); fma2(acc[2][1], q2, c1);
            fma2(acc[2][2], q2, c2); fma2(acc[2][3], q2, c3);
            fma2(acc[3][0], q3, c0); fma2(acc[3][1], q3, c1);
            fma2(acc[3][2], q3, c2); fma2(acc[3][3], q3, c3);
        }
#pragma unroll
        for (int i = 0; i < 4; i++) {
#pragma unroll
            for (int j = 0; j < 4; j++) {
                float lo, hi;
                unpack2(acc[i][j], lo, hi);
                float dot = lo + hi;
                sD[tr * 4 + i][tc * 4 + j] = ssq[tc * 4 + j] - 2.f * dot;
            }
        }
        __syncthreads();
        // insertion scan: each thread handles 16 candidates of its row
        int jb = half * 16;
#pragma unroll
        for (int i = 0; i < 16; i++) {
            float d2 = sD[myrow][jb + i];
            if (d2 < vals[KK - 1]) {
                vals[KK - 1] = d2;
                idxs[KK - 1] = j0g + jb + i;
#pragma unroll
                for (int p = KK - 1; p > 0; --p) {
                    bool s = vals[p] < vals[p - 1];  // ascending scan: strict < keeps low idx first
                    float va = vals[p - 1];
                    int ia = idxs[p - 1];
                    vals[p - 1] = s ? vals[p] : va;
                    idxs[p - 1] = s ? idxs[p] : ia;
                    vals[p] = s ? va : vals[p];
                    idxs[p] = s ? ia : idxs[p];
                }
            }
        }
    }

    // merge the two half-lists per row (halves interleave in j -> need idx tie-break)
    __syncthreads();
    int* iBuf = (int*)&sK[0][0];  // reuse; holds 64*KK ints
    if (half == 1) {
#pragma unroll
        for (int k = 0; k < KK; k++) {
            sD[myrow][k] = vals[k];
            iBuf[myrow * KK + k] = idxs[k];
        }
    }
    __syncthreads();
    if (half == 0) {
#pragma unroll
        for (int c = 0; c < KK; c++) {
            float v = sD[myrow][c];
            int ix = iBuf[myrow * KK + c];
            bool enter = (v < vals[KK - 1]) ||
                         (v == vals[KK - 1] && ix < idxs[KK - 1]);
            if (enter) {
                vals[KK - 1] = v;
                idxs[KK - 1] = ix;
#pragma unroll
                for (int p = KK - 1; p > 0; --p) {
                    bool s = (vals[p] < vals[p - 1]) ||
                             (vals[p] == vals[p - 1] && idxs[p] < idxs[p - 1]);
                    float va = vals[p - 1];
                    int ia = idxs[p - 1];
                    vals[p - 1] = s ? vals[p] : va;
                    idxs[p - 1] = s ? idxs[p] : ia;
                    vals[p] = s ? va : vals[p];
                    idxs[p] = s ? ia : idxs[p];
                }
            }
        }
        int base = (((bm * NN + row0 + myrow) << 2) | split) * KK;
#pragma unroll
        for (int k = 0; k < KK; k++) {
            g_pval[base + k] = vals[k];
            g_pidx[base + k] = idxs[k];
        }
    }
}

// ---------------- K2b: merge NSPLIT sorted top-10 lists -> final top-10 ----------------
__global__ void __launch_bounds__(256) k_merge() {
    int row = blockIdx.x * 256 + threadIdx.x;  // 0..BMT*NN-1
    if (row >= BMT * NN) return;
    int bm = row >> 10;
    float vals[KK];
    int idxs[KK];
#pragma unroll
    for (int k = 0; k < KK; k++) {
        vals[k] = __int_as_float(0x7f800000);
        idxs[k] = 0x7fffffff;
    }
    const float* pv = g_pval + (size_t)row * NSPLIT * KK;
    const int* pi = g_pidx + (size_t)row * NSPLIT * KK;
#pragma unroll
    for (int c = 0; c < NSPLIT * KK; c++) {
        float v = pv[c];
        int ix = pi[c];
        bool enter = (v < vals[KK - 1]) || (v == vals[KK - 1] && ix < idxs[KK - 1]);
        if (enter) {
            vals[KK - 1] = v;
            idxs[KK - 1] = ix;
#pragma unroll
            for (int p = KK - 1; p > 0; --p) {
                bool s = (vals[p] < vals[p - 1]) ||
                         (vals[p] == vals[p - 1] && idxs[p] < idxs[p - 1]);
                float va = vals[p - 1];
                int ia = idxs[p - 1];
                vals[p - 1] = s ? vals[p] : va;
                idxs[p - 1] = s ? idxs[p] : ia;
                vals[p] = s ? va : vals[p];
                idxs[p] = s ? ia : idxs[p];
            }
        }
    }
    int base = row * KK;
#pragma unroll
    for (int k = 0; k < KK; k++) {
        g_idx[base + k] = idxs[k];
        atomicAdd(&g_cnt[bm * NN + idxs[k]], 1);
    }
}

// ---------------- K5a: per-bm exclusive scan of counts ----------------
__global__ void __launch_bounds__(1024) k_scan() {
    int bm = blockIdx.x;
    __shared__ int s[NN];
    int t = threadIdx.x;
    int v = g_cnt[bm * NN + t];
    s[t] = v;
    __syncthreads();
    for (int off = 1; off < NN; off <<= 1) {
        int add = (t >= off) ? s[t - off] : 0;
        __syncthreads();
        s[t] += add;
        __syncthreads();
    }
    int excl = s[t] - v;
    g_start[bm * NN + t] = excl;
    g_fill[bm * NN + t] = excl;
}

// ---------------- K5b: fill CSR column lists ----------------
__global__ void k_fill() {
    int gid = blockIdx.x * blockDim.x + threadIdx.x;
    if (gid >= BMT * NN) return;
    int bm = gid >> 10;
    int n = gid & (NN - 1);
#pragma unroll
    for (int k = 0; k < KK; k++) {
        int j = g_idx[gid * KK + k];
        int pos = atomicAdd(&g_fill[bm * NN + j], 1);
        g_list[(size_t)bm * NN * KK + pos] = n;
    }
}

// ---------------- K6: edge aggregation  tmpE[bm,j,:] = De_inv * sum Xs[rows] ----------------
__global__ void __launch_bounds__(128) k_edge() {
    int j = blockIdx.x;
    int bm = blockIdx.y;
    int f = threadIdx.x;
    int cnt = g_cnt[bm * NN + j];
    int st = g_start[bm * NN + j];
    const int* lst = g_list + (size_t)bm * NN * KK + st;
    const float* Xb = g_Xs + (size_t)bm * NN * FF;
    float acc0 = 0.f, acc1 = 0.f, acc2v = 0.f, acc3 = 0.f;
    int i = 0;
    for (; i + 4 <= cnt; i += 4) {
        int n0 = lst[i], n1 = lst[i + 1], n2 = lst[i + 2], n3 = lst[i + 3];
        acc0 += Xb[(size_t)n0 * FF + f];
        acc1 += Xb[(size_t)n1 * FF + f];
        acc2v += Xb[(size_t)n2 * FF + f];
        acc3 += Xb[(size_t)n3 * FF + f];
    }
    for (; i < cnt; i++) acc0 += Xb[(size_t)lst[i] * FF + f];
    float acc = (acc0 + acc1) + (acc2v + acc3);
    float sc = (cnt > 0) ? (1.f / (float)cnt) : 0.f;
    g_tmpE[((size_t)bm * NN + j) * FF + f] = acc * sc;
}

// ---------------- K6b: cluster aggregation ----------------
__global__ void __launch_bounds__(128) k_cagg() {
    int bm = blockIdx.y;
    int base = blockIdx.x * 128;
    int f = threadIdx.x;
    __shared__ float sH[128 * NC];
    for (int t = f; t < 128 * NC; t += 128)
        sH[t] = g_Hc[((size_t)bm * NN + base) * NC + t];
    __syncthreads();
    float acc[NC] = {};
#pragma unroll 4
    for (int nn = 0; nn < 128; nn++) {
        float x = g_Xs[((size_t)bm * NN + base + nn) * FF + f];
#pragma unroll
        for (int c = 0; c < NC; c++) acc[c] = fmaf(sH[nn * NC + c], x, acc[c]);
    }
#pragma unroll
    for (int c = 0; c < NC; c++)
        atomicAdd(&g_tmpC[((size_t)bm * NC + c) * FF + f], acc[c]);
}

// ---------------- K7: final gather + cluster term + elu + output layout ----------------
__global__ void __launch_bounds__(128) k_final(float* __restrict__ out) {
    int bm = blockIdx.y;
    int base = blockIdx.x * 32;
    int f = threadIdx.x;
    __shared__ float sC[NC * FF];
    __shared__ float sH[32 * NC];
    __shared__ int sI[32 * KK];
    __shared__ float sDi[NC];
    if (f < NC) sDi[f] = 1.f / g_DeC[bm * NC + f];
    __syncthreads();
#pragma unroll
    for (int c = 0; c < NC; c++)
        sC[c * FF + f] = g_tmpC[((size_t)bm * NC + c) * FF + f] * sDi[c];
    for (int t = f; t < 32 * NC; t += 128) {
        sH[t] = g_Hc[((size_t)bm * NN + base) * NC + t];
        sI[t] = g_idx[((size_t)bm * NN + base) * KK + t];
    }
    __syncthreads();
    int b = bm >> 3, m = bm & 7;
    const float* Eb = g_tmpE + (size_t)bm * NN * FF;
#pragma unroll 2
    for (int r = 0; r < 32; r++) {
        float acc = 0.f;
#pragma unroll
        for (int k = 0; k < KK; k++) {
            int j = sI[r * KK + k];
            acc += Eb[(size_t)j * FF + f];
        }
#pragma unroll
        for (int c = 0; c < NC; c++)
            acc = fmaf(sH[r * NC + c], sC[c * FF + f], acc);
        float v = INV_SQRT11 * acc;
        v = (v > 0.f) ? v : expm1f(v);
        out[(((size_t)b * NN + base + r) * 8 + m) * FF + f] = v;
    }
}

// ---------------- launch ----------------
extern "C" void kernel_launch(void* const* d_in, const int* in_sizes, int n_in,
                              void* d_out, int out_size) {
    const float* x   = (const float*)d_in[0];  // [4,1024,8,128]
    const float* Wp  = (const float*)d_in[1];  // [64,128]
    const float* Wpb = (const float*)d_in[2];  // [64]
    const float* C   = (const float*)d_in[3];  // [10,64]
    const float* Tw  = (const float*)d_in[4];  // [128,128]
    const float* Tb  = (const float*)d_in[5];  // [128]
    float* out = (float*)d_out;

    k_gemm<0><<<dim3(BMT, NN / 64, 1), 128>>>(x, Wp, Wpb, 1.0f);             // 1: Z (+DeC zero)
    k_cluster_sq<<<(BMT * NN) / 256, 256>>>(C);                              // 2: softmax+sq+zeros
    k_knn<<<dim3(NN / 64, BMT * NSPLIT), 128>>>();                           // 3: Gram tiles + partial top-10
    k_merge<<<(BMT * NN) / 256, 256>>>();                                    // 4: merge + counts
    k_gemm<1><<<dim3(BMT, NN / 64, 2), 128>>>(x, Tw, Tb, INV_SQRT11);        // 5: Xs
    k_scan<<<BMT, 1024>>>();                                                 // 6
    k_fill<<<(BMT * NN + 255) / 256, 256>>>();                               // 7
    k_edge<<<dim3(NN, BMT), 128>>>();                                        // 8
    k_cagg<<<dim3(NN / 128, BMT), 128>>>();                                  // 9
    k_final<<<dim3(NN / 32, BMT), 128>>>(out);                               // 10
}

// round 5
// speedup vs baseline: 1.1689x; 1.1689x over previous
#include <cuda_runtime.h>
#include <math.h>

typedef unsigned long long ull;

// Problem constants
#define BMT 32      // B*M
#define NN 1024     // nodes
#define DD 128      // input dim
#define PP 64       // projection dim
#define NC 10       // clusters
#define FF 128      // output features
#define KK 10       // k neighbors
#define INV_SQRT11 0.30151134457776363f

// kNN tiling
#define ROWT 64
#define COLT 32
#define NKP2 (PP / 4)   // 16 quads of 4 floats (2 f32x2 pairs)

// ---------------- scratch (device globals: allocation-free) ----------------
__device__ ull   g_Zt[BMT * NKP2 * NN * 2];  // Z transposed: (bm, kp2, row) -> ull2 (4 floats)
__device__ float g_sq[BMT * NN];             // squared norms
__device__ int   g_idx[BMT * NN * KK];       // knn indices
__device__ float g_Hc[BMT * NN * NC];        // cluster softmax probs
__device__ float g_Xs[BMT * NN * FF];        // X_trans * 1/sqrt(11)
__device__ int   g_cnt[BMT * NN];            // per-edge degree of H_knn
__device__ int   g_start[BMT * NN];          // CSR starts
__device__ int   g_fill[BMT * NN];           // CSR fill cursors
__device__ int   g_list[BMT * NN * KK];      // CSR column lists
__device__ float g_tmpE[BMT * NN * FF];      // De_inv * (H_knn^T @ Xs)
__device__ float g_tmpC[BMT * NC * FF];      // H_cluster^T @ Xs (unscaled)
__device__ float g_DeC[BMT * NC];            // cluster edge degrees

// ---------------- f32x2 helpers ----------------
__device__ __forceinline__ void fma2(ull& d, ull a, ull b) {
    asm("fma.rn.f32x2 %0, %1, %2, %3;" : "=l"(d) : "l"(a), "l"(b), "l"(d));
}
__device__ __forceinline__ ull dup2(float a) {
    ull d;
    unsigned r = __float_as_uint(a);
    asm("mov.b64 %0, {%1, %1};" : "=l"(d) : "r"(r));
    return d;
}
__device__ __forceinline__ ull pack2(float lo, float hi) {
    ull d;
    asm("mov.b64 %0, {%1, %2};" : "=l"(d) : "r"(__float_as_uint(lo)), "r"(__float_as_uint(hi)));
    return d;
}
__device__ __forceinline__ void unpack2(ull v, float& lo, float& hi) {
    unsigned a, b;
    asm("mov.b64 {%0, %1}, %2;" : "=r"(a), "=r"(b) : "l"(v));
    lo = __uint_as_float(a);
    hi = __uint_as_float(b);
}

// ---------------- GEMM (f32x2 packed)
// MODE 0: Z -> g_Zt (transposed pair-packed), NCOLS=64
// MODE 1: Xs -> g_Xs row-major, NCOLS=128
template <int MODE>
__global__ void __launch_bounds__(128) k_gemm(const float* __restrict__ X,
                                              const float* __restrict__ W,
                                              const float* __restrict__ bias,
                                              float scale) {
    constexpr int NCOLS = (MODE == 0) ? PP : FF;
    __shared__ __align__(16) float sAT[32][72];  // [k][row]
    __shared__ __align__(16) float sWT[32][72];  // [k][col]
    int bm = blockIdx.x;
    int row0 = blockIdx.y * 64;
    int col0 = blockIdx.z * 64;
    int b = bm >> 3, m = bm & 7;
    int tid = threadIdx.x;
    // fold in g_DeC zeroing (must precede k_cluster_sq's atomics; MODE 0 runs first)
    if (MODE == 0 && blockIdx.x == 0 && blockIdx.y == 0 && blockIdx.z == 0) {
        for (int i = tid; i < BMT * NC; i += 128) g_DeC[i] = 0.f;
    }
    int tr = tid >> 3;  // 0..15 -> 4 rows each
    int tc = tid & 7;   // 0..7  -> 8 cols each
    ull acc2[4][4] = {};
    const float* xbase = X + ((size_t)(b * NN) * 8 + m) * DD;
    for (int k0 = 0; k0 < DD; k0 += 32) {
        for (int t = tid; t < 64 * 32; t += 128) {
            int r = t >> 5, k = t & 31;
            sAT[k][r] = xbase[(size_t)(row0 + r) * 1024 + k0 + k];
            sWT[k][r] = W[(col0 + r) * DD + k0 + k];
        }
        __syncthreads();
#pragma unroll
        for (int k = 0; k < 32; k++) {
            float4 a4 = *(const float4*)&sAT[k][tr * 4];
            ulonglong2 wA = *(const ulonglong2*)&sWT[k][tc * 8];
            ulonglong2 wB = *(const ulonglong2*)&sWT[k][tc * 8 + 4];
            ull a0 = dup2(a4.x), a1 = dup2(a4.y), a2 = dup2(a4.z), a3 = dup2(a4.w);
            fma2(acc2[0][0], a0, wA.x); fma2(acc2[0][1], a0, wA.y);
            fma2(acc2[0][2], a0, wB.x); fma2(acc2[0][3], a0, wB.y);
            fma2(acc2[1][0], a1, wA.x); fma2(acc2[1][1], a1, wA.y);
            fma2(acc2[1][2], a1, wB.x); fma2(acc2[1][3], a1, wB.y);
            fma2(acc2[2][0], a2, wA.x); fma2(acc2[2][1], a2, wA.y);
            fma2(acc2[2][2], a2, wB.x); fma2(acc2[2][3], a2, wB.y);
            fma2(acc2[3][0], a3, wA.x); fma2(acc2[3][1], a3, wA.y);
            fma2(acc2[3][2], a3, wB.x); fma2(acc2[3][3], a3, wB.y);
        }
        __syncthreads();
    }
    float bv[8];
#pragma unroll
    for (int j = 0; j < 8; j++) bv[j] = bias[col0 + tc * 8 + j];
#pragma unroll
    for (int i = 0; i < 4; i++) {
        int n = row0 + tr * 4 + i;
        float f[8];
#pragma unroll
        for (int j2 = 0; j2 < 4; j2++) unpack2(acc2[i][j2], f[2 * j2], f[2 * j2 + 1]);
#pragma unroll
        for (int j = 0; j < 8; j++) f[j] = (f[j] + bv[j]) * scale;
        if (MODE == 0) {
            // transposed pair-packed store: quad kp2 = tc*2 + {0,1}
            ulonglong2* zt2 = (ulonglong2*)g_Zt;
            ulonglong2 v0, v1;
            v0.x = pack2(f[0], f[1]); v0.y = pack2(f[2], f[3]);
            v1.x = pack2(f[4], f[5]); v1.y = pack2(f[6], f[7]);
            zt2[((size_t)(bm * NKP2 + tc * 2 + 0)) * NN + n] = v0;
            zt2[((size_t)(bm * NKP2 + tc * 2 + 1)) * NN + n] = v1;
        } else {
            float4 o0, o1;
            o0.x = f[0]; o0.y = f[1]; o0.z = f[2]; o0.w = f[3];
            o1.x = f[4]; o1.y = f[5]; o1.z = f[6]; o1.w = f[7];
            float* op = g_Xs + ((size_t)bm * NN + n) * NCOLS + col0 + tc * 8;
            *(float4*)op = o0;
            *(float4*)(op + 4) = o1;
        }
    }
}

// ---------------- K_cluster_sq: softmax + DeC + sq norm + zero cnt/tmpC ----
__global__ void __launch_bounds__(256) k_cluster_sq(const float* __restrict__ C) {
    __shared__ float sC[NC * PP];
    __shared__ float sDeC[NC];
    int tid = threadIdx.x;
    for (int t = tid; t < NC * PP; t += 256) sC[t] = C[t];
    if (tid < NC) sDeC[tid] = 0.f;
    __syncthreads();
    int row = blockIdx.x * 256 + tid;
    int bm = row >> 10;
    int n = row & (NN - 1);
    g_cnt[row] = 0;
    for (int i = row; i < BMT * NC * FF; i += BMT * NN) g_tmpC[i] = 0.f;
    const ulonglong2* zt2 = (const ulonglong2*)g_Zt;
    float acc[NC] = {};
    float sq = 0.f;
#pragma unroll
    for (int kp2 = 0; kp2 < NKP2; kp2++) {
        ulonglong2 v = zt2[((size_t)(bm * NKP2 + kp2)) * NN + n];
        float z0, z1, z2, z3;
        unpack2(v.x, z0, z1);
        unpack2(v.y, z2, z3);
        sq = fmaf(z0, z0, fmaf(z1, z1, fmaf(z2, z2, fmaf(z3, z3, sq))));
        const float* cp = &sC[kp2 * 4];
#pragma unroll
        for (int c = 0; c < NC; c++) {
            acc[c] = fmaf(z0, cp[c * PP + 0], acc[c]);
            acc[c] = fmaf(z1, cp[c * PP + 1], acc[c]);
            acc[c] = fmaf(z2, cp[c * PP + 2], acc[c]);
            acc[c] = fmaf(z3, cp[c * PP + 3], acc[c]);
        }
    }
    g_sq[row] = sq;
    float mx = acc[0];
#pragma unroll
    for (int c = 1; c < NC; c++) mx = fmaxf(mx, acc[c]);
    float p[NC], sum = 0.f;
#pragma unroll
    for (int c = 0; c < NC; c++) {
        p[c] = expf(acc[c] - mx);
        sum += p[c];
    }
    float inv = 1.f / sum;
#pragma unroll
    for (int c = 0; c < NC; c++) {
        p[c] *= inv;
        g_Hc[(size_t)row * NC + c] = p[c];
    }
#pragma unroll
    for (int c = 0; c < NC; c++)
#pragma unroll
        for (int o = 16; o; o >>= 1) p[c] += __shfl_xor_sync(0xffffffffu, p[c], o);
    if ((tid & 31) == 0) {
#pragma unroll
        for (int c = 0; c < NC; c++) atomicAdd(&sDeC[c], p[c]);
    }
    __syncthreads();
    if (tid < NC) atomicAdd(&g_DeC[bm * NC + tid], sDeC[tid]);
}

// ---------------- K2: FMA2-bound Gram tiles + in-kernel top-10 ----------------
// Block 128 thr: 64 rows x 32 cols per tile, thread = 4x4 f32x2 accs.
// Score = sq[j] - 2*dot (sq[i] dropped: constant per row, ordering-invariant).
__global__ void __launch_bounds__(128) k_knn() {
    int bm = blockIdx.y;
    int row0 = blockIdx.x * ROWT;

    __shared__ __align__(16) ulonglong2 sQ[NKP2][ROWT];  // 16KB
    __shared__ __align__(16) ulonglong2 sK[NKP2][COLT];  // 8KB
    __shared__ float sD[COLT][ROWT + 2];                 // 8.25KB
    __shared__ float ssq[COLT];
    __shared__ float sMv[ROWT][KK];                      // half-1 lists
    __shared__ int   sMi[ROWT][KK];

    const ulonglong2* zt2 = (const ulonglong2*)g_Zt + (size_t)bm * NKP2 * NN;
    int tid = threadIdx.x;

    // load query tile (coalesced: 64 consecutive ull2 per kp2)
#pragma unroll
    for (int e = tid; e < NKP2 * ROWT; e += 128) {
        int kp2 = e >> 6, r = e & 63;
        sQ[kp2][r] = zt2[(size_t)kp2 * NN + row0 + r];
    }

    int tr = tid >> 3;  // 0..15, rows tr + 16*i
    int tc = tid & 7;   // 0..7,  cols tc + 8*j
    int myrow = tid & 63;
    int half = tid >> 6;

    float vals[KK];
    int idxs[KK];
#pragma unroll
    for (int k = 0; k < KK; k++) {
        vals[k] = __int_as_float(0x7f800000);
        idxs[k] = 0x7fffffff;
    }

    for (int j0 = 0; j0 < NN; j0 += COLT) {
        // load candidate tile (32 consecutive ull2 per kp2)
#pragma unroll
        for (int e = tid; e < NKP2 * COLT; e += 128) {
            int kp2 = e >> 5, r = e & 31;
            sK[kp2][r] = zt2[(size_t)kp2 * NN + j0 + r];
        }
        if (tid < COLT) ssq[tid] = g_sq[bm * NN + j0 + tid];
        __syncthreads();

        ull acc[4][4] = {};
#pragma unroll
        for (int kp2 = 0; kp2 < NKP2; kp2++) {
            ulonglong2 q0 = sQ[kp2][tr + 0];
            ulonglong2 q1 = sQ[kp2][tr + 16];
            ulonglong2 q2 = sQ[kp2][tr + 32];
            ulonglong2 q3 = sQ[kp2][tr + 48];
            ulonglong2 c0 = sK[kp2][tc + 0];
            ulonglong2 c1 = sK[kp2][tc + 8];
            ulonglong2 c2 = sK[kp2][tc + 16];
            ulonglong2 c3 = sK[kp2][tc + 24];
            fma2(acc[0][0], q0.x, c0.x); fma2(acc[0][0], q0.y, c0.y);
            fma2(acc[0][1], q0.x, c1.x); fma2(acc[0][1], q0.y, c1.y);
            fma2(acc[0][2], q0.x, c2.x); fma2(acc[0][2], q0.y, c2.y);
            fma2(acc[0][3], q0.x, c3.x); fma2(acc[0][3], q0.y, c3.y);
            fma2(acc[1][0], q1.x, c0.x); fma2(acc[1][0], q1.y, c0.y);
            fma2(acc[1][1], q1.x, c1.x); fma2(acc[1][1], q1.y, c1.y);
            fma2(acc[1][2], q1.x, c2.x); fma2(acc[1][2], q1.y, c2.y);
            fma2(acc[1][3], q1.x, c3.x); fma2(acc[1][3], q1.y, c3.y);
            fma2(acc[2][0], q2.x, c0.x); fma2(acc[2][0], q2.y, c0.y);
            fma2(acc[2][1], q2.x, c1.x); fma2(acc[2][1], q2.y, c1.y);
            fma2(acc[2][2], q2.x, c2.x); fma2(acc[2][2], q2.y, c2.y);
            fma2(acc[2][3], q2.x, c3.x); fma2(acc[2][3], q2.y, c3.y);
            fma2(acc[3][0], q3.x, c0.x); fma2(acc[3][0], q3.y, c0.y);
            fma2(acc[3][1], q3.x, c1.x); fma2(acc[3][1], q3.y, c1.y);
            fma2(acc[3][2], q3.x, c2.x); fma2(acc[3][2], q3.y, c2.y);
            fma2(acc[3][3], q3.x, c3.x); fma2(acc[3][3], q3.y, c3.y);
        }
#pragma unroll
        for (int i = 0; i < 4; i++) {
#pragma unroll
            for (int j = 0; j < 4; j++) {
                float lo, hi;
                unpack2(acc[i][j], lo, hi);
                int col = tc + 8 * j;
                sD[col][tr + 16 * i] = fmaf(-2.f, lo + hi, ssq[col]);
            }
        }
        __syncthreads();

        // top-10 insertion: 2 threads per row, 16 cols each
        int cb = half * 16;
#pragma unroll
        for (int cc = 0; cc < 16; cc++) {
            float d2 = sD[cb + cc][myrow];
            if (d2 < vals[KK - 1]) {
                vals[KK - 1] = d2;
                idxs[KK - 1] = j0 + cb + cc;
#pragma unroll
                for (int p = KK - 1; p > 0; --p) {
                    bool s = vals[p] < vals[p - 1];  // ascending scan: strict < keeps low idx
                    float va = vals[p - 1];
                    int ia = idxs[p - 1];
                    vals[p - 1] = s ? vals[p] : va;
                    idxs[p - 1] = s ? idxs[p] : ia;
                    vals[p] = s ? va : vals[p];
                    idxs[p] = s ? ia : idxs[p];
                }
            }
        }
        __syncthreads();
    }

    // merge the two half-lists per row (halves interleave -> (val,idx) tie-break)
    if (half == 1) {
#pragma unroll
        for (int k = 0; k < KK; k++) {
            sMv[myrow][k] = vals[k];
            sMi[myrow][k] = idxs[k];
        }
    }
    __syncthreads();
    if (half == 0) {
#pragma unroll
        for (int c = 0; c < KK; c++) {
            float v = sMv[myrow][c];
            int ix = sMi[myrow][c];
            bool enter = (v < vals[KK - 1]) ||
                         (v == vals[KK - 1] && ix < idxs[KK - 1]);
            if (enter) {
                vals[KK - 1] = v;
                idxs[KK - 1] = ix;
#pragma unroll
                for (int p = KK - 1; p > 0; --p) {
                    bool s = (vals[p] < vals[p - 1]) ||
                             (vals[p] == vals[p - 1] && idxs[p] < idxs[p - 1]);
                    float va = vals[p - 1];
                    int ia = idxs[p - 1];
                    vals[p - 1] = s ? vals[p] : va;
                    idxs[p - 1] = s ? idxs[p] : ia;
                    vals[p] = s ? va : vals[p];
                    idxs[p] = s ? ia : idxs[p];
                }
            }
        }
        int base = (bm * NN + row0 + myrow) * KK;
#pragma unroll
        for (int k = 0; k < KK; k++) {
            g_idx[base + k] = idxs[k];
            atomicAdd(&g_cnt[bm * NN + idxs[k]], 1);
        }
    }
}

// ---------------- K5a: per-bm exclusive scan of counts ----------------
__global__ void __launch_bounds__(1024) k_scan() {
    int bm = blockIdx.x;
    __shared__ int s[NN];
    int t = threadIdx.x;
    int v = g_cnt[bm * NN + t];
    s[t] = v;
    __syncthreads();
    for (int off = 1; off < NN; off <<= 1) {
        int add = (t >= off) ? s[t - off] : 0;
        __syncthreads();
        s[t] += add;
        __syncthreads();
    }
    int excl = s[t] - v;
    g_start[bm * NN + t] = excl;
    g_fill[bm * NN + t] = excl;
}

// ---------------- K5b: fill CSR column lists ----------------
__global__ void k_fill() {
    int gid = blockIdx.x * blockDim.x + threadIdx.x;
    if (gid >= BMT * NN) return;
    int bm = gid >> 10;
    int n = gid & (NN - 1);
#pragma unroll
    for (int k = 0; k < KK; k++) {
        int j = g_idx[gid * KK + k];
        int pos = atomicAdd(&g_fill[bm * NN + j], 1);
        g_list[(size_t)bm * NN * KK + pos] = n;
    }
}

// ---------------- K6: edge aggregation ----------------
__global__ void __launch_bounds__(128) k_edge() {
    int j = blockIdx.x;
    int bm = blockIdx.y;
    int f = threadIdx.x;
    int cnt = g_cnt[bm * NN + j];
    int st = g_start[bm * NN + j];
    const int* lst = g_list + (size_t)bm * NN * KK + st;
    const float* Xb = g_Xs + (size_t)bm * NN * FF;
    float acc0 = 0.f, acc1 = 0.f, acc2v = 0.f, acc3 = 0.f;
    int i = 0;
    for (; i + 4 <= cnt; i += 4) {
        int n0 = lst[i], n1 = lst[i + 1], n2 = lst[i + 2], n3 = lst[i + 3];
        acc0 += Xb[(size_t)n0 * FF + f];
        acc1 += Xb[(size_t)n1 * FF + f];
        acc2v += Xb[(size_t)n2 * FF + f];
        acc3 += Xb[(size_t)n3 * FF + f];
    }
    for (; i < cnt; i++) acc0 += Xb[(size_t)lst[i] * FF + f];
    float acc = (acc0 + acc1) + (acc2v + acc3);
    float sc = (cnt > 0) ? (1.f / (float)cnt) : 0.f;
    g_tmpE[((size_t)bm * NN + j) * FF + f] = acc * sc;
}

// ---------------- K6b: cluster aggregation ----------------
__global__ void __launch_bounds__(128) k_cagg() {
    int bm = blockIdx.y;
    int base = blockIdx.x * 128;
    int f = threadIdx.x;
    __shared__ float sH[128 * NC];
    for (int t = f; t < 128 * NC; t += 128)
        sH[t] = g_Hc[((size_t)bm * NN + base) * NC + t];
    __syncthreads();
    float acc[NC] = {};
#pragma unroll 4
    for (int nn = 0; nn < 128; nn++) {
        float x = g_Xs[((size_t)bm * NN + base + nn) * FF + f];
#pragma unroll
        for (int c = 0; c < NC; c++) acc[c] = fmaf(sH[nn * NC + c], x, acc[c]);
    }
#pragma unroll
    for (int c = 0; c < NC; c++)
        atomicAdd(&g_tmpC[((size_t)bm * NC + c) * FF + f], acc[c]);
}

// ---------------- K7: final gather + cluster term + elu + output layout ----------------
__global__ void __launch_bounds__(128) k_final(float* __restrict__ out) {
    int bm = blockIdx.y;
    int base = blockIdx.x * 32;
    int f = threadIdx.x;
    __shared__ float sC[NC * FF];
    __shared__ float sH[32 * NC];
    __shared__ int sI[32 * KK];
    __shared__ float sDi[NC];
    if (f < NC) sDi[f] = 1.f / g_DeC[bm * NC + f];
    __syncthreads();
#pragma unroll
    for (int c = 0; c < NC; c++)
        sC[c * FF + f] = g_tmpC[((size_t)bm * NC + c) * FF + f] * sDi[c];
    for (int t = f; t < 32 * NC; t += 128) {
        sH[t] = g_Hc[((size_t)bm * NN + base) * NC + t];
        sI[t] = g_idx[((size_t)bm * NN + base) * KK + t];
    }
    __syncthreads();
    int b = bm >> 3, m = bm & 7;
    const float* Eb = g_tmpE + (size_t)bm * NN * FF;
#pragma unroll 2
    for (int r = 0; r < 32; r++) {
        float acc = 0.f;
#pragma unroll
        for (int k = 0; k < KK; k++) {
            int j = sI[r * KK + k];
            acc += Eb[(size_t)j * FF + f];
        }
#pragma unroll
        for (int c = 0; c < NC; c++)
            acc = fmaf(sH[r * NC + c], sC[c * FF + f], acc);
        float v = INV_SQRT11 * acc;
        v = (v > 0.f) ? v : expm1f(v);
        out[(((size_t)b * NN + base + r) * 8 + m) * FF + f] = v;
    }
}

// ---------------- launch ----------------
extern "C" void kernel_launch(void* const* d_in, const int* in_sizes, int n_in,
                              void* d_out, int out_size) {
    const float* x   = (const float*)d_in[0];  // [4,1024,8,128]
    const float* Wp  = (const float*)d_in[1];  // [64,128]
    const float* Wpb = (const float*)d_in[2];  // [64]
    const float* C   = (const float*)d_in[3];  // [10,64]
    const float* Tw  = (const float*)d_in[4];  // [128,128]
    const float* Tb  = (const float*)d_in[5];  // [128]
    float* out = (float*)d_out;

    k_gemm<0><<<dim3(BMT, NN / 64, 1), 128>>>(x, Wp, Wpb, 1.0f);             // 1: Zt (+DeC zero)
    k_cluster_sq<<<(BMT * NN) / 256, 256>>>(C);                              // 2: softmax+sq+zeros
    k_knn<<<dim3(NN / ROWT, BMT), 128>>>();                                  // 3: Gram + top-10 + counts
    k_gemm<1><<<dim3(BMT, NN / 64, 2), 128>>>(x, Tw, Tb, INV_SQRT11);        // 4: Xs
    k_scan<<<BMT, 1024>>>();                                                 // 5
    k_fill<<<(BMT * NN + 255) / 256, 256>>>();                               // 6
    k_edge<<<dim3(NN, BMT), 128>>>();                                        // 7
    k_cagg<<<dim3(NN / 128, BMT), 128>>>();                                  // 8
    k_final<<<dim3(NN / 32, BMT), 128>>>(out);                               // 9
}

// round 6
// speedup vs baseline: 1.2063x; 1.0320x over previous
#include <cuda_runtime.h>
#include <math.h>

typedef unsigned long long ull;

// Problem constants
#define BMT 32      // B*M
#define NN 1024     // nodes
#define DD 128      // input dim
#define PP 64       // projection dim
#define NC 10       // clusters
#define FF 128      // output features
#define KK 10       // k neighbors
#define INV_SQRT11 0.30151134457776363f

// kNN tiling
#define ROWT 64
#define COLT 32
#define NKP2 (PP / 4)   // 16 quads of 4 floats (2 f32x2 pairs)

// ---------------- scratch (device globals: allocation-free) ----------------
__device__ ull   g_Zt[BMT * NKP2 * NN * 2];  // Z transposed: (bm, kp2, row) -> ull2 (4 floats)
__device__ float g_sq[BMT * NN];             // squared norms
__device__ int   g_idx[BMT * NN * KK];       // knn indices
__device__ float g_Hc[BMT * NN * NC];        // cluster softmax probs
__device__ float g_Xs[BMT * NN * FF];        // X_trans * 1/sqrt(11)
__device__ int   g_cnt[BMT * NN];            // per-edge degree of H_knn
__device__ int   g_start[BMT * NN];          // CSR starts
__device__ int   g_fill[BMT * NN];           // CSR fill cursors
__device__ int   g_list[BMT * NN * KK];      // CSR column lists
__device__ float g_tmpE[BMT * NN * FF];      // De_inv * (H_knn^T @ Xs)
__device__ float g_tmpC[BMT * NC * FF];      // H_cluster^T @ Xs (unscaled)
__device__ float g_DeC[BMT * NC];            // cluster edge degrees

// ---------------- f32x2 helpers ----------------
__device__ __forceinline__ void fma2(ull& d, ull a, ull b) {
    asm("fma.rn.f32x2 %0, %1, %2, %3;" : "=l"(d) : "l"(a), "l"(b), "l"(d));
}
__device__ __forceinline__ ull pack2(float lo, float hi) {
    ull d;
    asm("mov.b64 %0, {%1, %2};" : "=l"(d) : "r"(__float_as_uint(lo)), "r"(__float_as_uint(hi)));
    return d;
}
__device__ __forceinline__ void unpack2(ull v, float& lo, float& hi) {
    unsigned a, b;
    asm("mov.b64 {%0, %1}, %2;" : "=r"(a), "=r"(b) : "l"(v));
    lo = __uint_as_float(a);
    hi = __uint_as_float(b);
}
__device__ __forceinline__ void cpa16(unsigned s, const void* g) {
    asm volatile("cp.async.cg.shared.global [%0], [%1], 16;" :: "r"(s), "l"(g));
}

// ---------------- GEMM: cp.async double-buffered, pair-packed smem ----------
// Tile: 64 rows x 64 cols, 128 threads, thread = 4 rows x 8 cols (col pairs).
// MODE 0: Z -> g_Zt (transposed pair-packed).  MODE 1: Xs -> g_Xs row-major.
template <int MODE>
__global__ void __launch_bounds__(128, 4) k_gemm(const float* __restrict__ X,
                                                 const float* __restrict__ W,
                                                 const float* __restrict__ bias,
                                                 float scale) {
    __shared__ __align__(16) char smem_raw[32768];
    ulonglong2* sAp = (ulonglong2*)smem_raw;            // [2][8][64] = 16 KB
    ulonglong2* sWp = (ulonglong2*)(smem_raw + 16384);  // [2][8][64] = 16 KB

    int bm = blockIdx.x;
    int row0 = blockIdx.y * 64;
    int col0 = blockIdx.z * 64;
    int b = bm >> 3, m = bm & 7;
    int tid = threadIdx.x;
    if (MODE == 0 && blockIdx.x == 0 && blockIdx.y == 0) {
        for (int i = tid; i < BMT * NC; i += 128) g_DeC[i] = 0.f;
    }
    const float* xbase = X + ((size_t)(b * NN) * 8 + m) * DD;

    unsigned sA_u = (unsigned)__cvta_generic_to_shared(sAp);
    unsigned sW_u = (unsigned)__cvta_generic_to_shared(sWp);

    // per-thread load coords: 4 ull2 each for A and W per chunk
    int lr = tid & 63;          // row / col
    int lk = tid >> 6;          // kp2 base (0 or 1), + {0,2,4,6}

    // issue one chunk's cp.asyncs (8 kp2 quads of 32 k)
    auto issue = [&](int ch) {
        int st = ch & 1;
#pragma unroll
        for (int q = 0; q < 4; q++) {
            int kp2 = lk + 2 * q;
            unsigned sa = sA_u + ((st * 8 + kp2) * 64 + lr) * 16;
            cpa16(sa, xbase + (size_t)(row0 + lr) * 1024 + ch * 32 + kp2 * 4);
            unsigned sw = sW_u + ((st * 8 + kp2) * 64 + lr) * 16;
            cpa16(sw, W + (size_t)(col0 + lr) * DD + ch * 32 + kp2 * 4);
        }
        asm volatile("cp.async.commit_group;");
    };

    int tr = tid >> 3;  // 0..15 -> rows tr + 16*i
    int tc = tid & 7;   // cols: (p*16) + tc*2 + {0,1}
    int cols[8];
#pragma unroll
    for (int ci = 0; ci < 8; ci++) cols[ci] = ((ci >> 1) << 4) + tc * 2 + (ci & 1);

    ull acc[4][8] = {};

    issue(0);
#pragma unroll
    for (int ch = 0; ch < 4; ch++) {
        if (ch < 3) {
            issue(ch + 1);
            asm volatile("cp.async.wait_group 1;");
        } else {
            asm volatile("cp.async.wait_group 0;");
        }
        __syncthreads();
        int st = ch & 1;
#pragma unroll
        for (int kp2 = 0; kp2 < 8; kp2++) {
            const ulonglong2* ab = sAp + (st * 8 + kp2) * 64;
            const ulonglong2* wb = sWp + (st * 8 + kp2) * 64;
            ulonglong2 a0 = ab[tr + 0];
            ulonglong2 a1 = ab[tr + 16];
            ulonglong2 a2 = ab[tr + 32];
            ulonglong2 a3 = ab[tr + 48];
#pragma unroll
            for (int ci = 0; ci < 8; ci++) {
                ulonglong2 w = wb[cols[ci]];
                fma2(acc[0][ci], a0.x, w.x); fma2(acc[0][ci], a0.y, w.y);
                fma2(acc[1][ci], a1.x, w.x); fma2(acc[1][ci], a1.y, w.y);
                fma2(acc[2][ci], a2.x, w.x); fma2(acc[2][ci], a2.y, w.y);
                fma2(acc[3][ci], a3.x, w.x); fma2(acc[3][ci], a3.y, w.y);
            }
        }
        __syncthreads();
    }

    float bv[8];
#pragma unroll
    for (int ci = 0; ci < 8; ci++) bv[ci] = bias[col0 + cols[ci]];

    if (MODE == 1) {
#pragma unroll
        for (int i = 0; i < 4; i++) {
            int n = row0 + tr + 16 * i;
            float* op = g_Xs + ((size_t)bm * NN + n) * FF + col0;
#pragma unroll
            for (int p = 0; p < 4; p++) {
                float l0, h0, l1, h1;
                unpack2(acc[i][2 * p], l0, h0);
                unpack2(acc[i][2 * p + 1], l1, h1);
                float2 v;
                v.x = (l0 + h0 + bv[2 * p]) * scale;
                v.y = (l1 + h1 + bv[2 * p + 1]) * scale;
                *(float2*)(op + p * 16 + tc * 2) = v;
            }
        }
    } else {
        // transpose epilogue: sT[col][row] with 66-float row pad (conflict-free)
        float* sT = (float*)smem_raw;  // 64*66*4 = 16.9 KB <= 32 KB
#pragma unroll
        for (int i = 0; i < 4; i++) {
            int r = tr + 16 * i;
#pragma unroll
            for (int ci = 0; ci < 8; ci++) {
                float lo, hi;
                unpack2(acc[i][ci], lo, hi);
                sT[cols[ci] * 66 + r] = (lo + hi + bv[ci]) * scale;
            }
        }
        __syncthreads();
        ulonglong2* zt2 = (ulonglong2*)g_Zt;
#pragma unroll
        for (int e = tid; e < 64 * NKP2; e += 128) {
            int kp2 = e >> 6, r = e & 63;
            float z0 = sT[(kp2 * 4 + 0) * 66 + r];
            float z1 = sT[(kp2 * 4 + 1) * 66 + r];
            float z2 = sT[(kp2 * 4 + 2) * 66 + r];
            float z3 = sT[(kp2 * 4 + 3) * 66 + r];
            ulonglong2 v;
            v.x = pack2(z0, z1);
            v.y = pack2(z2, z3);
            zt2[((size_t)(bm * NKP2 + kp2)) * NN + row0 + r] = v;
        }
    }
}

// ---------------- K_cluster_sq: softmax + DeC + sq norm + zero cnt/tmpC ----
__global__ void __launch_bounds__(256) k_cluster_sq(const float* __restrict__ C) {
    __shared__ float sC[NC * PP];
    __shared__ float sDeC[NC];
    int tid = threadIdx.x;
    for (int t = tid; t < NC * PP; t += 256) sC[t] = C[t];
    if (tid < NC) sDeC[tid] = 0.f;
    __syncthreads();
    int row = blockIdx.x * 256 + tid;
    int bm = row >> 10;
    int n = row & (NN - 1);
    g_cnt[row] = 0;
    for (int i = row; i < BMT * NC * FF; i += BMT * NN) g_tmpC[i] = 0.f;
    const ulonglong2* zt2 = (const ulonglong2*)g_Zt;
    float acc[NC] = {};
    float sq = 0.f;
#pragma unroll
    for (int kp2 = 0; kp2 < NKP2; kp2++) {
        ulonglong2 v = zt2[((size_t)(bm * NKP2 + kp2)) * NN + n];
        float z0, z1, z2, z3;
        unpack2(v.x, z0, z1);
        unpack2(v.y, z2, z3);
        sq = fmaf(z0, z0, fmaf(z1, z1, fmaf(z2, z2, fmaf(z3, z3, sq))));
        const float* cp = &sC[kp2 * 4];
#pragma unroll
        for (int c = 0; c < NC; c++) {
            acc[c] = fmaf(z0, cp[c * PP + 0], acc[c]);
            acc[c] = fmaf(z1, cp[c * PP + 1], acc[c]);
            acc[c] = fmaf(z2, cp[c * PP + 2], acc[c]);
            acc[c] = fmaf(z3, cp[c * PP + 3], acc[c]);
        }
    }
    g_sq[row] = sq;
    float mx = acc[0];
#pragma unroll
    for (int c = 1; c < NC; c++) mx = fmaxf(mx, acc[c]);
    float p[NC], sum = 0.f;
#pragma unroll
    for (int c = 0; c < NC; c++) {
        p[c] = expf(acc[c] - mx);
        sum += p[c];
    }
    float inv = 1.f / sum;
#pragma unroll
    for (int c = 0; c < NC; c++) {
        p[c] *= inv;
        g_Hc[(size_t)row * NC + c] = p[c];
    }
#pragma unroll
    for (int c = 0; c < NC; c++)
#pragma unroll
        for (int o = 16; o; o >>= 1) p[c] += __shfl_xor_sync(0xffffffffu, p[c], o);
    if ((tid & 31) == 0) {
#pragma unroll
        for (int c = 0; c < NC; c++) atomicAdd(&sDeC[c], p[c]);
    }
    __syncthreads();
    if (tid < NC) atomicAdd(&g_DeC[bm * NC + tid], sDeC[tid]);
}

// ---------------- K2: FMA2-bound Gram tiles + in-kernel top-10 ----------------
__global__ void __launch_bounds__(128) k_knn() {
    int bm = blockIdx.y;
    int row0 = blockIdx.x * ROWT;

    __shared__ __align__(16) ulonglong2 sQ[NKP2][ROWT];  // 16KB
    __shared__ __align__(16) ulonglong2 sK[NKP2][COLT];  // 8KB
    __shared__ float sD[COLT][ROWT + 2];                 // 8.25KB
    __shared__ float ssq[COLT];
    __shared__ float sMv[ROWT][KK];
    __shared__ int   sMi[ROWT][KK];

    const ulonglong2* zt2 = (const ulonglong2*)g_Zt + (size_t)bm * NKP2 * NN;
    int tid = threadIdx.x;

#pragma unroll
    for (int e = tid; e < NKP2 * ROWT; e += 128) {
        int kp2 = e >> 6, r = e & 63;
        sQ[kp2][r] = zt2[(size_t)kp2 * NN + row0 + r];
    }

    int tr = tid >> 3;
    int tc = tid & 7;
    int myrow = tid & 63;
    int half = tid >> 6;

    float vals[KK];
    int idxs[KK];
#pragma unroll
    for (int k = 0; k < KK; k++) {
        vals[k] = __int_as_float(0x7f800000);
        idxs[k] = 0x7fffffff;
    }

    for (int j0 = 0; j0 < NN; j0 += COLT) {
#pragma unroll
        for (int e = tid; e < NKP2 * COLT; e += 128) {
            int kp2 = e >> 5, r = e & 31;
            sK[kp2][r] = zt2[(size_t)kp2 * NN + j0 + r];
        }
        if (tid < COLT) ssq[tid] = g_sq[bm * NN + j0 + tid];
        __syncthreads();

        ull acc[4][4] = {};
#pragma unroll
        for (int kp2 = 0; kp2 < NKP2; kp2++) {
            ulonglong2 q0 = sQ[kp2][tr + 0];
            ulonglong2 q1 = sQ[kp2][tr + 16];
            ulonglong2 q2 = sQ[kp2][tr + 32];
            ulonglong2 q3 = sQ[kp2][tr + 48];
            ulonglong2 c0 = sK[kp2][tc + 0];
            ulonglong2 c1 = sK[kp2][tc + 8];
            ulonglong2 c2 = sK[kp2][tc + 16];
            ulonglong2 c3 = sK[kp2][tc + 24];
            fma2(acc[0][0], q0.x, c0.x); fma2(acc[0][0], q0.y, c0.y);
            fma2(acc[0][1], q0.x, c1.x); fma2(acc[0][1], q0.y, c1.y);
            fma2(acc[0][2], q0.x, c2.x); fma2(acc[0][2], q0.y, c2.y);
            fma2(acc[0][3], q0.x, c3.x); fma2(acc[0][3], q0.y, c3.y);
            fma2(acc[1][0], q1.x, c0.x); fma2(acc[1][0], q1.y, c0.y);
            fma2(acc[1][1], q1.x, c1.x); fma2(acc[1][1], q1.y, c1.y);
            fma2(acc[1][2], q1.x, c2.x); fma2(acc[1][2], q1.y, c2.y);
            fma2(acc[1][3], q1.x, c3.x); fma2(acc[1][3], q1.y, c3.y);
            fma2(acc[2][0], q2.x, c0.x); fma2(acc[2][0], q2.y, c0.y);
            fma2(acc[2][1], q2.x, c1.x); fma2(acc[2][1], q2.y, c1.y);
            fma2(acc[2][2], q2.x, c2.x); fma2(acc[2][2], q2.y, c2.y);
            fma2(acc[2][3], q2.x, c3.x); fma2(acc[2][3], q2.y, c3.y);
            fma2(acc[3][0], q3.x, c0.x); fma2(acc[3][0], q3.y, c0.y);
            fma2(acc[3][1], q3.x, c1.x); fma2(acc[3][1], q3.y, c1.y);
            fma2(acc[3][2], q3.x, c2.x); fma2(acc[3][2], q3.y, c2.y);
            fma2(acc[3][3], q3.x, c3.x); fma2(acc[3][3], q3.y, c3.y);
        }
#pragma unroll
        for (int i = 0; i < 4; i++) {
#pragma unroll
            for (int j = 0; j < 4; j++) {
                float lo, hi;
                unpack2(acc[i][j], lo, hi);
                int col = tc + 8 * j;
                sD[col][tr + 16 * i] = fmaf(-2.f, lo + hi, ssq[col]);
            }
        }
        __syncthreads();

        int cb = half * 16;
#pragma unroll
        for (int cc = 0; cc < 16; cc++) {
            float d2 = sD[cb + cc][myrow];
            if (d2 < vals[KK - 1]) {
                vals[KK - 1] = d2;
                idxs[KK - 1] = j0 + cb + cc;
#pragma unroll
                for (int p = KK - 1; p > 0; --p) {
                    bool s = vals[p] < vals[p - 1];
                    float va = vals[p - 1];
                    int ia = idxs[p - 1];
                    vals[p - 1] = s ? vals[p] : va;
                    idxs[p - 1] = s ? idxs[p] : ia;
                    vals[p] = s ? va : vals[p];
                    idxs[p] = s ? ia : idxs[p];
                }
            }
        }
        __syncthreads();
    }

    if (half == 1) {
#pragma unroll
        for (int k = 0; k < KK; k++) {
            sMv[myrow][k] = vals[k];
            sMi[myrow][k] = idxs[k];
        }
    }
    __syncthreads();
    if (half == 0) {
#pragma unroll
        for (int c = 0; c < KK; c++) {
            float v = sMv[myrow][c];
            int ix = sMi[myrow][c];
            bool enter = (v < vals[KK - 1]) ||
                         (v == vals[KK - 1] && ix < idxs[KK - 1]);
            if (enter) {
                vals[KK - 1] = v;
                idxs[KK - 1] = ix;
#pragma unroll
                for (int p = KK - 1; p > 0; --p) {
                    bool s = (vals[p] < vals[p - 1]) ||
                             (vals[p] == vals[p - 1] && idxs[p] < idxs[p - 1]);
                    float va = vals[p - 1];
                    int ia = idxs[p - 1];
                    vals[p - 1] = s ? vals[p] : va;
                    idxs[p - 1] = s ? idxs[p] : ia;
                    vals[p] = s ? va : vals[p];
                    idxs[p] = s ? ia : idxs[p];
                }
            }
        }
        int base = (bm * NN + row0 + myrow) * KK;
#pragma unroll
        for (int k = 0; k < KK; k++) {
            g_idx[base + k] = idxs[k];
            atomicAdd(&g_cnt[bm * NN + idxs[k]], 1);
        }
    }
}

// ---------------- K5a: per-bm exclusive scan of counts ----------------
__global__ void __launch_bounds__(1024) k_scan() {
    int bm = blockIdx.x;
    __shared__ int s[NN];
    int t = threadIdx.x;
    int v = g_cnt[bm * NN + t];
    s[t] = v;
    __syncthreads();
    for (int off = 1; off < NN; off <<= 1) {
        int add = (t >= off) ? s[t - off] : 0;
        __syncthreads();
        s[t] += add;
        __syncthreads();
    }
    int excl = s[t] - v;
    g_start[bm * NN + t] = excl;
    g_fill[bm * NN + t] = excl;
}

// ---------------- K5b: fill CSR column lists ----------------
__global__ void k_fill() {
    int gid = blockIdx.x * blockDim.x + threadIdx.x;
    if (gid >= BMT * NN) return;
    int bm = gid >> 10;
    int n = gid & (NN - 1);
#pragma unroll
    for (int k = 0; k < KK; k++) {
        int j = g_idx[gid * KK + k];
        int pos = atomicAdd(&g_fill[bm * NN + j], 1);
        g_list[(size_t)bm * NN * KK + pos] = n;
    }
}

// ---------------- K6: edge aggregation ----------------
__global__ void __launch_bounds__(128) k_edge() {
    int j = blockIdx.x;
    int bm = blockIdx.y;
    int f = threadIdx.x;
    int cnt = g_cnt[bm * NN + j];
    int st = g_start[bm * NN + j];
    const int* lst = g_list + (size_t)bm * NN * KK + st;
    const float* Xb = g_Xs + (size_t)bm * NN * FF;
    float acc0 = 0.f, acc1 = 0.f, acc2v = 0.f, acc3 = 0.f;
    int i = 0;
    for (; i + 4 <= cnt; i += 4) {
        int n0 = lst[i], n1 = lst[i + 1], n2 = lst[i + 2], n3 = lst[i + 3];
        acc0 += Xb[(size_t)n0 * FF + f];
        acc1 += Xb[(size_t)n1 * FF + f];
        acc2v += Xb[(size_t)n2 * FF + f];
        acc3 += Xb[(size_t)n3 * FF + f];
    }
    for (; i < cnt; i++) acc0 += Xb[(size_t)lst[i] * FF + f];
    float acc = (acc0 + acc1) + (acc2v + acc3);
    float sc = (cnt > 0) ? (1.f / (float)cnt) : 0.f;
    g_tmpE[((size_t)bm * NN + j) * FF + f] = acc * sc;
}

// ---------------- K6b: cluster aggregation ----------------
__global__ void __launch_bounds__(128) k_cagg() {
    int bm = blockIdx.y;
    int base = blockIdx.x * 128;
    int f = threadIdx.x;
    __shared__ float sH[128 * NC];
    for (int t = f; t < 128 * NC; t += 128)
        sH[t] = g_Hc[((size_t)bm * NN + base) * NC + t];
    __syncthreads();
    float acc[NC] = {};
#pragma unroll 4
    for (int nn = 0; nn < 128; nn++) {
        float x = g_Xs[((size_t)bm * NN + base + nn) * FF + f];
#pragma unroll
        for (int c = 0; c < NC; c++) acc[c] = fmaf(sH[nn * NC + c], x, acc[c]);
    }
#pragma unroll
    for (int c = 0; c < NC; c++)
        atomicAdd(&g_tmpC[((size_t)bm * NC + c) * FF + f], acc[c]);
}

// ---------------- K7: final gather + cluster term + elu + output layout ----------------
__global__ void __launch_bounds__(128) k_final(float* __restrict__ out) {
    int bm = blockIdx.y;
    int base = blockIdx.x * 32;
    int f = threadIdx.x;
    __shared__ float sC[NC * FF];
    __shared__ float sH[32 * NC];
    __shared__ int sI[32 * KK];
    __shared__ float sDi[NC];
    if (f < NC) sDi[f] = 1.f / g_DeC[bm * NC + f];
    __syncthreads();
#pragma unroll
    for (int c = 0; c < NC; c++)
        sC[c * FF + f] = g_tmpC[((size_t)bm * NC + c) * FF + f] * sDi[c];
    for (int t = f; t < 32 * NC; t += 128) {
        sH[t] = g_Hc[((size_t)bm * NN + base) * NC + t];
        sI[t] = g_idx[((size_t)bm * NN + base) * KK + t];
    }
    __syncthreads();
    int b = bm >> 3, m = bm & 7;
    const float* Eb = g_tmpE + (size_t)bm * NN * FF;
#pragma unroll 2
    for (int r = 0; r < 32; r++) {
        float acc = 0.f;
#pragma unroll
        for (int k = 0; k < KK; k++) {
            int j = sI[r * KK + k];
            acc += Eb[(size_t)j * FF + f];
        }
#pragma unroll
        for (int c = 0; c < NC; c++)
            acc = fmaf(sH[r * NC + c], sC[c * FF + f], acc);
        float v = INV_SQRT11 * acc;
        v = (v > 0.f) ? v : expm1f(v);
        out[(((size_t)b * NN + base + r) * 8 + m) * FF + f] = v;
    }
}

// ---------------- launch ----------------
extern "C" void kernel_launch(void* const* d_in, const int* in_sizes, int n_in,
                              void* d_out, int out_size) {
    const float* x   = (const float*)d_in[0];  // [4,1024,8,128]
    const float* Wp  = (const float*)d_in[1];  // [64,128]
    const float* Wpb = (const float*)d_in[2];  // [64]
    const float* C   = (const float*)d_in[3];  // [10,64]
    const float* Tw  = (const float*)d_in[4];  // [128,128]
    const float* Tb  = (const float*)d_in[5];  // [128]
    float* out = (float*)d_out;

    k_gemm<0><<<dim3(BMT, NN / 64, 1), 128>>>(x, Wp, Wpb, 1.0f);             // 1: Zt (+DeC zero)
    k_cluster_sq<<<(BMT * NN) / 256, 256>>>(C);                              // 2: softmax+sq+zeros
    k_knn<<<dim3(NN / ROWT, BMT), 128>>>();                                  // 3: Gram + top-10 + counts
    k_gemm<1><<<dim3(BMT, NN / 64, 2), 128>>>(x, Tw, Tb, INV_SQRT11);        // 4: Xs
    k_scan<<<BMT, 1024>>>();                                                 // 5
    k_fill<<<(BMT * NN + 255) / 256, 256>>>();                               // 6
    k_edge<<<dim3(NN, BMT), 128>>>();                                        // 7
    k_cagg<<<dim3(NN / 128, BMT), 128>>>();                                  // 8
    k_final<<<dim3(NN / 32, BMT), 128>>>(out);                               // 9
}